// round 11
// baseline (speedup 1.0000x reference)
#include <cuda_runtime.h>
#include <math.h>

#define TLEN 262144
#define KST  64
#define FDIM 16
#define LCH  512
#define WARM 64
#define STEPS (WARM + LCH)     // 576
#define TILE 8
#define NTILES (STEPS / TILE)  // 72
#define NCH  (TLEN / LCH)      // 512
#define GCH  2                 // chunks per 64-thread group
#define EPSV 1e-10
#define LOGEPSF (-23.0258509299f)

// ---- scratch (__device__ globals; no cudaMalloc allowed) ----
__device__ float  g_E   [(size_t)TLEN * KST];
__device__ float  g_dirF[(size_t)TLEN * KST];
__device__ float  g_dirB[(size_t)TLEN * KST];
__device__ float  g_cF[TLEN];
__device__ float  g_fB[TLEN];
__device__ float  g_rhoF[TLEN];
__device__ float  g_rhoB[TLEN];
__device__ float  g_wtmp[NCH * KST];   // bwd pre-emission dir at last warm step
__device__ float  g_lam[NCH];          // its sum (boundary handoff scale)
__device__ double g_S[2 * TLEN];       // prefix sums of log(eps/c), fb-major
__device__ double g_LM[2 * TLEN];      // prefix-LSE max part
__device__ float  g_LS[2 * TLEN];      // prefix-LSE sum part (value = m + log s)
__device__ double g_part[1024];
__device__ double g_p2m[1024];
__device__ float  g_p2s[1024];
__device__ float  g_scF[TLEN], g_scB[TLEN];   // g_scB indexed in m-space
__device__ int    g_pad[4];

typedef unsigned long long u64t;

__device__ __forceinline__ void fma2(u64t& acc, u64t a, u64t b) {
    asm("fma.rn.f32x2 %0, %1, %2, %3;" : "=l"(acc) : "l"(a), "l"(b), "l"(acc));
}
__device__ __forceinline__ void add2(u64t& d, u64t a, u64t b) {
    asm("add.rn.f32x2 %0, %1, %2;" : "=l"(d) : "l"(a), "l"(b));
}
__device__ __forceinline__ u64t pack2(float lo, float hi) {
    u64t r;
    asm("mov.b64 %0, {%1, %2};" : "=l"(r) : "f"(lo), "f"(hi));
    return r;
}
__device__ __forceinline__ float unpack_sum(u64t v) {
    float lo, hi;
    asm("mov.b64 {%0, %1}, %2;" : "=f"(lo), "=f"(hi) : "l"(v));
    return lo + hi;
}
__device__ __forceinline__ float pow2inv(float r) {
    unsigned b = __float_as_uint(r);
    unsigned e = (b >> 23) & 0xffu;
    return __uint_as_float((254u - e) << 23);
}

__device__ __forceinline__ void cp16(void* dst, const void* src) {
    unsigned ds = (unsigned)__cvta_generic_to_shared(dst);
    asm volatile("cp.async.ca.shared.global [%0], [%1], 16;" :: "r"(ds), "l"(src));
}
#define CP_COMMIT() asm volatile("cp.async.commit_group;")
#define CP_WAIT(n)  asm volatile("cp.async.wait_group %0;" :: "n"(n))
#define BARC(id)    asm volatile("bar.sync %0, 64;" :: "r"(id) : "memory")

__device__ __forceinline__ int clampr(int row) {
    row = row < 0 ? 0 : row;
    return row > TLEN - 1 ? TLEN - 1 : row;
}

// ---------------------------------------------------------------------------
// Pad kernels: keep chunk_kernel in ncu's capture slot (launch index 3)
// ---------------------------------------------------------------------------
__global__ void pad_kernel(int which) {
    if (threadIdx.x == 0) g_pad[which] = which;
}

// ---------------------------------------------------------------------------
// Emission: 16 time rows per block
// ---------------------------------------------------------------------------
__global__ void emis_kernel(const float* __restrict__ obs,
                            const float* __restrict__ means,
                            const float* __restrict__ logvars) {
    __shared__ float mu_s[FDIM][KST];
    __shared__ float iv_s[FDIM][KST];
    __shared__ float ck_s[KST];
    __shared__ float xo_s[16][FDIM];
    const float LOG2PI = 1.8378770664093453f;
    int tid = threadIdx.x;

    for (int idx = tid; idx < KST * FDIM; idx += 256) {
        int k = idx >> 4, f = idx & 15;
        mu_s[f][k] = means[idx];
        iv_s[f][k] = expf(-logvars[idx]);
    }
    if (tid < KST) {
        float s = 0.f;
        #pragma unroll
        for (int f = 0; f < FDIM; f++) s += logvars[tid * FDIM + f];
        ck_s[tid] = -0.5f * s - 0.5f * (float)FDIM * LOG2PI;
    }
    int t0 = blockIdx.x * 16;
    xo_s[tid >> 4][tid & 15] = obs[(size_t)t0 * FDIM + tid];
    __syncthreads();

    int k = tid & 63, tb = tid >> 6;
    #pragma unroll
    for (int i = 0; i < 4; i++) {
        int tl = tb * 4 + i;
        float acc = 0.f;
        #pragma unroll
        for (int f = 0; f < FDIM; f++) {
            float d = xo_s[tl][f] - mu_s[f][k];
            acc = fmaf(d * d, iv_s[f][k], acc);
        }
        g_E[(size_t)(t0 + tl) * KST + k] = expf(-0.5f * acc + ck_s[k]);
    }
}

// ---------------------------------------------------------------------------
// Chunk kernel: each block = fwd group (threads 0..63) + bwd group (64..127).
// Each group runs GCH=2 chunks concurrently, sharing register-resident P.
// TILE=8 keeps static smem under the 48KB cap.
// ---------------------------------------------------------------------------
__global__ void __launch_bounds__(128, 2) chunk_kernel(
    const float* __restrict__ pi_logits,
    const float* __restrict__ beta_logits) {
    __shared__ float Pa[KST * KST];
    __shared__ float rm[KST], ri[KST];
    __shared__ __align__(16) float Ebuf[2][2][GCH][TILE][KST];   // 16 KB
    __shared__ __align__(16) float dbuf[2][GCH][2][KST];         // [ch][c][par][k]

    int tid = threadIdx.x;
    int ch = tid >> 6;
    int jj = tid & 63;
    const int barid = ch + 1;

    const int cb0 = blockIdx.x * GCH;
    int sout0[GCH], sfirst0[GCH], sfa[GCH];
    #pragma unroll
    for (int c = 0; c < GCH; c++) {
        sout0[c] = (cb0 + c) * LCH;
        sfirst0[c] = sout0[c] - WARM;
        sfa[c] = (cb0 + c == 0) ? 1 : sfirst0[c];
    }

    // prefetch tile 0 for both chains of this group (TILE*64/4/64 = 2 cp16 per chain per thread)
    #pragma unroll
    for (int c = 0; c < GCH; c++) {
        #pragma unroll
        for (int i = 0; i < TILE * KST / 4 / 64; i++) {
            int f4 = i * 64 + jj;
            int q = f4 >> 4, k0 = (f4 & 15) << 2;
            int s = sfirst0[c] + q;
            int row = clampr(ch ? (TLEN - 1 - s) : s);
            cp16(&Ebuf[0][ch][c][q][k0], g_E + (size_t)row * KST + k0);
        }
    }
    CP_COMMIT();

    for (int idx = tid; idx < KST * KST; idx += 128) Pa[idx] = pi_logits[idx];
    __syncthreads();
    if (tid < KST) {
        float m = -1e30f;
        for (int i = 0; i < KST; i++) m = fmaxf(m, Pa[tid * KST + i]);
        float s = 0.f;
        for (int i = 0; i < KST; i++) s += expf(Pa[tid * KST + i] - m);
        rm[tid] = m; ri[tid] = 1.f / s;
    }
    __syncthreads();

    u64t Preg2[32];
    if (ch == 0) {
        #pragma unroll
        for (int ii = 0; ii < 32; ii++) {
            float lo = expf(Pa[(2 * ii) * KST + jj] - rm[2 * ii]) * ri[2 * ii];
            float hi = expf(Pa[(2 * ii + 1) * KST + jj] - rm[2 * ii + 1]) * ri[2 * ii + 1];
            Preg2[ii] = pack2(lo, hi);
        }
    } else {
        #pragma unroll
        for (int ii = 0; ii < 32; ii++) {
            float lo = expf(Pa[jj * KST + 2 * ii] - rm[jj]) * ri[jj];
            float hi = expf(Pa[jj * KST + 2 * ii + 1] - rm[jj]) * ri[jj];
            Preg2[ii] = pack2(lo, hi);
        }
    }

    // ---- init carried state for both chains ----
    #pragma unroll
    for (int c = 0; c < GCH; c++) {
        int cb = cb0 + c;
        if (ch == 0) {
            float w0;
            if (cb == 0) {
                float pr = 1.f;
                for (int i = 0; i < jj; i++) {
                    float sg = 1.f / (1.f + expf(-beta_logits[i]));
                    pr *= (1.f - sg);
                }
                float bw = pr / (1.f + expf(-beta_logits[jj]));
                w0 = bw * g_E[jj];
                g_dirF[jj] = w0;
            } else {
                w0 = 1.f / 64.f;
            }
            dbuf[0][c][0][jj] = w0; dbuf[0][c][1][jj] = w0;
        } else {
            float z0;
            if (cb == 0) {
                z0 = (1.f / 64.f) * g_E[(size_t)(TLEN - 1) * KST + jj];
                g_dirB[(size_t)(TLEN - 1) * KST + jj] = 1.f / 64.f;
            } else {
                int tws = TLEN - sfirst0[c];
                tws = tws > TLEN - 1 ? TLEN - 1 : tws;
                z0 = (1.f / 64.f) * g_E[(size_t)tws * KST + jj];
            }
            dbuf[1][c][0][jj] = z0; dbuf[1][c][1][jj] = z0;
        }
    }
    __syncthreads();

    float rnorm[GCH];
    #pragma unroll
    for (int c = 0; c < GCH; c++) rnorm[c] = 1.f;
    int par = 0;

    for (int tb = 0; tb < NTILES; tb++) {
        if (tb + 1 < NTILES) {
            #pragma unroll
            for (int c = 0; c < GCH; c++) {
                #pragma unroll
                for (int i = 0; i < TILE * KST / 4 / 64; i++) {
                    int f4 = i * 64 + jj;
                    int q = f4 >> 4, k0 = (f4 & 15) << 2;
                    int s = sfirst0[c] + (tb + 1) * TILE + q;
                    int row = clampr(ch ? (TLEN - 1 - s) : s);
                    cp16(&Ebuf[(tb + 1) & 1][ch][c][q][k0], g_E + (size_t)row * KST + k0);
                }
            }
            CP_COMMIT();
            CP_WAIT(1);
        } else {
            CP_WAIT(0);
        }
        BARC(barid);

        #pragma unroll 2
        for (int st = 0; st < TILE; st++) {
            int np = par ^ 1;
            #pragma unroll
            for (int c = 0; c < GCH; c++) {
                int s = sfirst0[c] + tb * TILE + st;

                const ulonglong2* dc = reinterpret_cast<const ulonglong2*>(&dbuf[ch][c][par][0]);
                u64t a0 = 0, a1 = 0, a2 = 0, a3 = 0;
                u64t s0 = 0, s1 = 0, s2 = 0, s3 = 0;
                #pragma unroll
                for (int q = 0; q < 16; q += 2) {
                    ulonglong2 v = dc[q];
                    ulonglong2 w = dc[q + 1];
                    fma2(a0, v.x, Preg2[2 * q]);
                    fma2(a1, v.y, Preg2[2 * q + 1]);
                    fma2(a2, w.x, Preg2[2 * q + 2]);
                    fma2(a3, w.y, Preg2[2 * q + 3]);
                    add2(s0, s0, v.x); add2(s1, s1, v.y);
                    add2(s2, s2, w.x); add2(s3, s3, w.y);
                }
                add2(a0, a0, a1); add2(a2, a2, a3); add2(a0, a0, a2);
                float acc = unpack_sum(a0);
                add2(s0, s0, s1); add2(s2, s2, s3); add2(s0, s0, s2);
                float rho = unpack_sum(s0);
                float f = pow2inv(rho);
                float e = Ebuf[tb & 1][ch][c][st][jj];

                if (s >= sfa[c]) {
                    int cb = cb0 + c;
                    if (ch == 0) {
                        float wv = acc * f * e;
                        dbuf[0][c][np][jj] = wv;
                        if (s >= sout0[c]) g_dirF[(size_t)s * KST + jj] = wv;
                        if (jj == 0) {
                            int t = s - 1;
                            if (t == 0) { g_cF[0] = rho; g_rhoF[0] = rho; }
                            else if (t >= sout0[c]) {
                                g_cF[t] = __fdividef(rho, rnorm[c]);
                                g_rhoF[t] = rho;
                            }
                        }
                    } else {
                        float wv = acc * f;
                        dbuf[1][c][np][jj] = wv * e;
                        if (s >= sout0[c]) {
                            g_dirB[(size_t)(TLEN - 1 - s) * KST + jj] = wv;
                            if (jj == 0) g_fB[s] = f;
                        } else if (s == sout0[c] - 1) {
                            g_wtmp[cb * KST + jj] = wv;
                        }
                    }
                    rnorm[c] = f * rho;
                }
            }
            par = np;
            BARC(barid);
        }
    }

    // fwd: final rho/c for t = send-1 of each chain
    if (ch == 0) {
        #pragma unroll
        for (int c = 0; c < GCH; c++) {
            const ulonglong2* dc = reinterpret_cast<const ulonglong2*>(&dbuf[0][c][par][0]);
            u64t s0 = 0, s1 = 0, s2 = 0, s3 = 0;
            #pragma unroll
            for (int q = 0; q < 16; q += 2) {
                ulonglong2 v = dc[q];
                ulonglong2 w = dc[q + 1];
                add2(s0, s0, v.x); add2(s1, s1, v.y);
                add2(s2, s2, w.x); add2(s3, s3, w.y);
            }
            add2(s0, s0, s1); add2(s2, s2, s3); add2(s0, s0, s2);
            float rho = unpack_sum(s0);
            if (jj == 0) {
                int send = sout0[c] + LCH;
                g_cF[send - 1] = __fdividef(rho, rnorm[c]);
                g_rhoF[send - 1] = rho;
            }
        }
    }
}

// ---------------------------------------------------------------------------
// rsum (blocks 0..1023) + lam (blocks 1024..1087) fused into one launch
// ---------------------------------------------------------------------------
__global__ void rsum_lam_kernel() {
    if (blockIdx.x < TLEN / 256) {
        int m = blockIdx.x * 256 + threadIdx.x;
        const float4* r = reinterpret_cast<const float4*>(&g_dirB[(size_t)(TLEN - 1 - m) * KST]);
        float s = 0.f;
        #pragma unroll
        for (int i = 0; i < 16; i++) {
            float4 v = r[i];
            s += (v.x + v.y) + (v.z + v.w);
        }
        g_rhoB[m] = s;
    } else {
        int gw = ((blockIdx.x - TLEN / 256) * blockDim.x + threadIdx.x) >> 5;
        int lane = threadIdx.x & 31;
        if (gw >= NCH) return;
        float s = g_wtmp[gw * KST + lane] + g_wtmp[gw * KST + 32 + lane];
        s += __shfl_xor_sync(0xffffffffu, s, 16);
        s += __shfl_xor_sync(0xffffffffu, s, 8);
        s += __shfl_xor_sync(0xffffffffu, s, 4);
        s += __shfl_xor_sync(0xffffffffu, s, 2);
        s += __shfl_xor_sync(0xffffffffu, s, 1);
        if (lane == 0) g_lam[gw] = s;
    }
}

// ---------------------------------------------------------------------------
// Scans. S = f64 prefix sum of v_t = log(eps/c_t) (v computed in f32).
// Prefix-LSE of G_j = -S_j held as (m:f64, s:f32), value = m + log s.
// ---------------------------------------------------------------------------
__global__ void scan_k1() {
    __shared__ double sm[512];
    int fb = blockIdx.x >> 9, blk = blockIdx.x & 511;
    int tid = threadIdx.x, idx = blk * 512 + tid;
    double v;
    if (idx == 0) v = 0.0;
    else if (fb == 0) v = (double)(LOGEPSF - logf(g_cF[idx]));
    else {
        float Rprev = (tid == 0) ? g_lam[blk] : g_rhoB[idx - 1];
        float c = g_rhoB[idx] / (g_fB[idx] * Rprev);
        v = (double)(LOGEPSF - logf(c));
    }
    sm[tid] = v; __syncthreads();
    for (int off = 1; off < 512; off <<= 1) {
        double t = (tid >= off) ? sm[tid - off] : 0.0;
        __syncthreads();
        sm[tid] += t; __syncthreads();
    }
    g_S[fb * TLEN + idx] = sm[tid];
    if (tid == 511) g_part[blockIdx.x] = sm[tid];
}
__global__ void scan_k2() {
    __shared__ double sm[512];
    int tid = threadIdx.x;
    double* p = g_part + blockIdx.x * 512;
    sm[tid] = p[tid]; __syncthreads();
    for (int off = 1; off < 512; off <<= 1) {
        double t = (tid >= off) ? sm[tid - off] : 0.0;
        __syncthreads();
        sm[tid] += t; __syncthreads();
    }
    p[tid] = (tid == 0) ? 0.0 : sm[tid - 1];
}
__global__ void scan_k3() {
    __shared__ double sm_m[512];
    __shared__ float  sm_s[512];
    int fb = blockIdx.x >> 9, blk = blockIdx.x & 511;
    int tid = threadIdx.x, idx = blk * 512 + tid;
    double s_loc = g_S[fb * TLEN + idx] + g_part[blockIdx.x];
    g_S[fb * TLEN + idx] = s_loc;
    double gm;
    if (idx == 0) gm = fb ? -log(64.0) : log1p(EPSV / (double)g_cF[0]);
    else          gm = -s_loc;
    sm_m[tid] = gm; sm_s[tid] = 1.0f;
    __syncthreads();
    for (int off = 1; off < 512; off <<= 1) {
        double pm; float ps;
        if (tid >= off) { pm = sm_m[tid - off]; ps = sm_s[tid - off]; }
        else            { pm = -1e300; ps = 0.f; }
        __syncthreads();
        double cm = sm_m[tid]; float cs = sm_s[tid];
        if (pm > cm) { sm_m[tid] = pm; sm_s[tid] = ps + cs * expf((float)(cm - pm)); }
        else         {                 sm_s[tid] = cs + ps * expf((float)(pm - cm)); }
        __syncthreads();
    }
    g_LM[fb * TLEN + idx] = sm_m[tid];
    g_LS[fb * TLEN + idx] = sm_s[tid];
    if (tid == 511) { g_p2m[blockIdx.x] = sm_m[tid]; g_p2s[blockIdx.x] = sm_s[tid]; }
}
__global__ void scan_k4() {
    __shared__ double sm_m[512];
    __shared__ float  sm_s[512];
    int tid = threadIdx.x;
    int base = blockIdx.x * 512;
    sm_m[tid] = g_p2m[base + tid]; sm_s[tid] = g_p2s[base + tid];
    __syncthreads();
    for (int off = 1; off < 512; off <<= 1) {
        double pm; float ps;
        if (tid >= off) { pm = sm_m[tid - off]; ps = sm_s[tid - off]; }
        else            { pm = -1e300; ps = 0.f; }
        __syncthreads();
        double cm = sm_m[tid]; float cs = sm_s[tid];
        if (pm > cm) { sm_m[tid] = pm; sm_s[tid] = ps + cs * expf((float)(cm - pm)); }
        else         {                 sm_s[tid] = cs + ps * expf((float)(pm - cm)); }
        __syncthreads();
    }
    if (tid == 0) { g_p2m[base] = -1e300; g_p2s[base] = 0.f; }
    else          { g_p2m[base + tid] = sm_m[tid - 1]; g_p2s[base + tid] = sm_s[tid - 1]; }
}
__global__ void scan_k5(float* __restrict__ out) {
    int fb = blockIdx.x >> 9, blk = blockIdx.x & 511;
    int idx = blk * 512 + threadIdx.x;
    double Lm = g_LM[fb * TLEN + idx]; float Ls = g_LS[fb * TLEN + idx];
    double pm = g_p2m[blockIdx.x];     float ps = g_p2s[blockIdx.x];
    double m; float s;
    if (pm > Lm) { m = pm; s = ps + Ls * expf((float)(Lm - pm)); }
    else         { m = Lm; s = Ls + ps * expf((float)(pm - Lm)); }
    double lq = g_S[fb * TLEN + idx] + m + (double)logf(s);
    float rho = fb ? g_rhoB[idx] : g_rhoF[idx];
    float lqf = (lq > 200.0) ? 200.0f : (float)lq;
    float sc = expf(-lqf) / rho;
    if (lq > 150.0) sc = 0.f;
    (fb ? g_scB : g_scF)[idx] = sc;
    if (fb == 0 && idx == TLEN - 1)
        out[(size_t)2 * TLEN * KST] = (float)log(exp(-lq) + EPSV);
}

// ---------------------------------------------------------------------------
// Finalize: skip dir-row loads where the scale is exactly zero (most rows)
// ---------------------------------------------------------------------------
__global__ void finalize_kernel(float* __restrict__ out) {
    size_t i4 = ((size_t)blockIdx.x * 256 + threadIdx.x) * 4;
    int t = (int)(i4 >> 6);
    float sF = g_scF[t];
    float sB = g_scB[TLEN - 1 - t];
    float4 a = make_float4(0.f, 0.f, 0.f, 0.f);
    float4 b = make_float4(0.f, 0.f, 0.f, 0.f);
    if (sF != 0.f) {
        a = *reinterpret_cast<const float4*>(&g_dirF[i4]);
        a.x *= sF; a.y *= sF; a.z *= sF; a.w *= sF;
    }
    if (sB != 0.f) {
        b = *reinterpret_cast<const float4*>(&g_dirB[i4]);
        b.x *= sB; b.y *= sB; b.z *= sB; b.w *= sB;
    }
    *reinterpret_cast<float4*>(&out[i4]) = a;
    *reinterpret_cast<float4*>(&out[(size_t)TLEN * KST + i4]) = b;
}

// ---------------------------------------------------------------------------
extern "C" void kernel_launch(void* const* d_in, const int* in_sizes, int n_in,
                              void* d_out, int out_size) {
    const float* obs      = (const float*)d_in[0];
    const float* blogits  = (const float*)d_in[1];
    const float* pilogits = (const float*)d_in[2];
    const float* means    = (const float*)d_in[3];
    const float* logvars  = (const float*)d_in[4];
    float* out = (float*)d_out;

    pad_kernel<<<1, 32>>>(0);                 // launch idx 0
    pad_kernel<<<1, 32>>>(1);                 // launch idx 1
    emis_kernel<<<TLEN / 16, 256>>>(obs, means, logvars);   // idx 2
    chunk_kernel<<<NCH / GCH, 128>>>(pilogits, blogits);    // idx 3 <- ncu capture slot
    rsum_lam_kernel<<<TLEN / 256 + 64, 256>>>();
    scan_k1<<<1024, 512>>>();
    scan_k2<<<2, 512>>>();
    scan_k3<<<1024, 512>>>();
    scan_k4<<<2, 512>>>();
    scan_k5<<<1024, 512>>>(out);
    finalize_kernel<<<(size_t)TLEN * KST / 1024, 256>>>(out);
}

// round 13
// speedup vs baseline: 1.2935x; 1.2935x over previous
#include <cuda_runtime.h>
#include <math.h>

#define TLEN 262144
#define KST  64
#define FDIM 16
#define LCH  512
#define WARM 64
#define STEPS (WARM + LCH)     // 576
#define TILE 8
#define NTILES (STEPS / TILE)  // 72
#define NCH  (TLEN / LCH)      // 512
#define EPSV 1e-10
#define LOGEPSF (-23.0258509299f)

// ---- scratch (__device__ globals; no cudaMalloc allowed) ----
__device__ float  g_E   [(size_t)TLEN * KST];
__device__ float  g_P   [KST * KST];   // softmaxed pi, row-major
__device__ float  g_PT  [KST * KST];   // transpose of g_P
__device__ float  g_dirF[(size_t)TLEN * KST];
__device__ float  g_dirB[(size_t)TLEN * KST];
__device__ float  g_cF[TLEN];
__device__ float  g_fB[TLEN];
__device__ float  g_rhoF[TLEN];
__device__ float  g_rhoB[TLEN];
__device__ float  g_wtmp[NCH * KST];   // bwd pre-emission dir at last warm step
__device__ float  g_lam[NCH];          // its sum (boundary handoff scale)
__device__ double g_S[2 * TLEN];       // prefix sums of log(eps/c), fb-major
__device__ double g_LM[2 * TLEN];      // prefix-LSE max part
__device__ float  g_LS[2 * TLEN];      // prefix-LSE sum part (value = m + log s)
__device__ double g_part[1024];
__device__ double g_p2m[1024];
__device__ float  g_p2s[1024];
__device__ float  g_scF[TLEN], g_scB[TLEN];   // g_scB indexed in m-space
__device__ int    g_pad[4];

typedef unsigned long long u64t;

__device__ __forceinline__ void fma2(u64t& acc, u64t a, u64t b) {
    asm("fma.rn.f32x2 %0, %1, %2, %3;" : "=l"(acc) : "l"(a), "l"(b), "l"(acc));
}
__device__ __forceinline__ void add2(u64t& d, u64t a, u64t b) {
    asm("add.rn.f32x2 %0, %1, %2;" : "=l"(d) : "l"(a), "l"(b));
}
__device__ __forceinline__ float unpack_sum(u64t v) {
    float lo, hi;
    asm("mov.b64 {%0, %1}, %2;" : "=f"(lo), "=f"(hi) : "l"(v));
    return lo + hi;
}
__device__ __forceinline__ float pow2inv(float r) {
    unsigned b = __float_as_uint(r);
    unsigned e = (b >> 23) & 0xffu;
    return __uint_as_float((254u - e) << 23);
}

__device__ __forceinline__ void cp16(void* dst, const void* src) {
    unsigned ds = (unsigned)__cvta_generic_to_shared(dst);
    asm volatile("cp.async.ca.shared.global [%0], [%1], 16;" :: "r"(ds), "l"(src));
}
#define CP_COMMIT() asm volatile("cp.async.commit_group;")
#define CP_WAIT(n)  asm volatile("cp.async.wait_group %0;" :: "n"(n))

__device__ __forceinline__ int clampr(int row) {
    row = row < 0 ? 0 : row;
    return row > TLEN - 1 ? TLEN - 1 : row;
}

// ---------------------------------------------------------------------------
__global__ void pad_kernel(int which) {
    if (threadIdx.x == 0) g_pad[which] = which;
}

// ---------------------------------------------------------------------------
// Emission: 16 time rows per block
// ---------------------------------------------------------------------------
__global__ void emis_kernel(const float* __restrict__ obs,
                            const float* __restrict__ means,
                            const float* __restrict__ logvars) {
    __shared__ float mu_s[FDIM][KST];
    __shared__ float iv_s[FDIM][KST];
    __shared__ float ck_s[KST];
    __shared__ float xo_s[16][FDIM];
    const float LOG2PI = 1.8378770664093453f;
    int tid = threadIdx.x;

    for (int idx = tid; idx < KST * FDIM; idx += 256) {
        int k = idx >> 4, f = idx & 15;
        mu_s[f][k] = means[idx];
        iv_s[f][k] = expf(-logvars[idx]);
    }
    if (tid < KST) {
        float s = 0.f;
        #pragma unroll
        for (int f = 0; f < FDIM; f++) s += logvars[tid * FDIM + f];
        ck_s[tid] = -0.5f * s - 0.5f * (float)FDIM * LOG2PI;
    }
    int t0 = blockIdx.x * 16;
    xo_s[tid >> 4][tid & 15] = obs[(size_t)t0 * FDIM + tid];
    __syncthreads();

    int k = tid & 63, tb = tid >> 6;
    #pragma unroll
    for (int i = 0; i < 4; i++) {
        int tl = tb * 4 + i;
        float acc = 0.f;
        #pragma unroll
        for (int f = 0; f < FDIM; f++) {
            float d = xo_s[tl][f] - mu_s[f][k];
            acc = fmaf(d * d, iv_s[f][k], acc);
        }
        g_E[(size_t)(t0 + tl) * KST + k] = expf(-0.5f * acc + ck_s[k]);
    }
}

// ---------------------------------------------------------------------------
// Precompute softmax(P) and its transpose once.
// ---------------------------------------------------------------------------
__global__ void pk_kernel(const float* __restrict__ pi_logits) {
    int r = threadIdx.x;   // 64 threads, one row each
    float row[KST];
    float m = -1e30f;
    #pragma unroll
    for (int i = 0; i < KST; i++) {
        row[i] = pi_logits[r * KST + i];
        m = fmaxf(m, row[i]);
    }
    float s = 0.f;
    #pragma unroll
    for (int i = 0; i < KST; i++) { row[i] = expf(row[i] - m); s += row[i]; }
    float inv = 1.f / s;
    #pragma unroll
    for (int i = 0; i < KST; i++) {
        float v = row[i] * inv;
        g_P[r * KST + i] = v;
        g_PT[i * KST + r] = v;
    }
}

// ---------------------------------------------------------------------------
// Chunk kernel: ONE WARP per chain (barrier-free). blockIdx < NCH: fwd chunk;
// else bwd. Lane owns states j0 = 2*lane, j0+1. P in registers (f32x2 pairs).
// Intra-warp sync via __syncwarp only.
// ---------------------------------------------------------------------------
__global__ void __launch_bounds__(32, 8) chunk_kernel(
    const float* __restrict__ beta_logits) {
    __shared__ __align__(16) float Ebuf[2][TILE][KST];
    __shared__ __align__(16) float dbuf[2][KST];

    int lane = threadIdx.x;
    const bool bwd = (blockIdx.x >= NCH);
    const int cb = bwd ? (int)blockIdx.x - NCH : (int)blockIdx.x;
    const int j0 = lane * 2;

    const int sout0 = cb * LCH;
    const int sfirst0 = sout0 - WARM;
    const int sfa = (cb == 0) ? 1 : sfirst0;
    const int send = sout0 + LCH;

    // prefetch tile 0 (4 cp16 per lane)
    #pragma unroll
    for (int i = 0; i < 4; i++) {
        int f4 = i * 32 + lane;
        int q = f4 >> 4, k0 = (f4 & 15) << 2;
        int row = clampr(bwd ? (TLEN - 1 - (sfirst0 + q)) : (sfirst0 + q));
        cp16(&Ebuf[0][q][k0], g_E + (size_t)row * KST + k0);
    }
    CP_COMMIT();

    // P into registers: 2 rows of (bwd ? g_P : g_PT), packed as f32x2 pairs.
    const float* rowA = (bwd ? g_P : g_PT) + j0 * KST;
    const float* rowB = rowA + KST;
    u64t PA[32], PB[32];
    {
        const ulonglong2* pa = reinterpret_cast<const ulonglong2*>(rowA);
        const ulonglong2* pb = reinterpret_cast<const ulonglong2*>(rowB);
        #pragma unroll
        for (int q = 0; q < 16; q++) {
            ulonglong2 va = pa[q]; PA[2 * q] = va.x; PA[2 * q + 1] = va.y;
            ulonglong2 vb = pb[q]; PB[2 * q] = vb.x; PB[2 * q + 1] = vb.y;
        }
    }

    // ---- init carried state (both parities) ----
    if (!bwd) {
        float w0, w1;
        if (cb == 0) {
            float pr = 1.f; w0 = 0.f; w1 = 0.f;
            for (int j = 0; j <= j0 + 1; j++) {
                float sg = 1.f / (1.f + expf(-beta_logits[j]));
                if (j == j0) w0 = pr * sg;
                else if (j == j0 + 1) w1 = pr * sg;
                pr *= (1.f - sg);
            }
            w0 *= g_E[j0]; w1 *= g_E[j0 + 1];
            *reinterpret_cast<float2*>(&g_dirF[j0]) = make_float2(w0, w1);
        } else {
            w0 = 1.f / 64.f; w1 = 1.f / 64.f;
        }
        *reinterpret_cast<float2*>(&dbuf[0][j0]) = make_float2(w0, w1);
        *reinterpret_cast<float2*>(&dbuf[1][j0]) = make_float2(w0, w1);
    } else {
        float z0, z1;
        if (cb == 0) {
            z0 = (1.f / 64.f) * g_E[(size_t)(TLEN - 1) * KST + j0];
            z1 = (1.f / 64.f) * g_E[(size_t)(TLEN - 1) * KST + j0 + 1];
            *reinterpret_cast<float2*>(&g_dirB[(size_t)(TLEN - 1) * KST + j0]) =
                make_float2(1.f / 64.f, 1.f / 64.f);
        } else {
            int tws = clampr(TLEN - sfirst0);
            z0 = (1.f / 64.f) * g_E[(size_t)tws * KST + j0];
            z1 = (1.f / 64.f) * g_E[(size_t)tws * KST + j0 + 1];
        }
        *reinterpret_cast<float2*>(&dbuf[0][j0]) = make_float2(z0, z1);
        *reinterpret_cast<float2*>(&dbuf[1][j0]) = make_float2(z0, z1);
    }
    __syncwarp();

    float rnorm = 1.f;
    int par = 0;

    for (int tb = 0; tb < NTILES; tb++) {
        if (tb + 1 < NTILES) {
            #pragma unroll
            for (int i = 0; i < 4; i++) {
                int f4 = i * 32 + lane;
                int q = f4 >> 4, k0 = (f4 & 15) << 2;
                int s = sfirst0 + (tb + 1) * TILE + q;
                int row = clampr(bwd ? (TLEN - 1 - s) : s);
                cp16(&Ebuf[(tb + 1) & 1][q][k0], g_E + (size_t)row * KST + k0);
            }
            CP_COMMIT();
            CP_WAIT(1);
        } else {
            CP_WAIT(0);
        }
        __syncwarp();

        #pragma unroll 2
        for (int st = 0; st < TILE; st++) {
            int s = sfirst0 + tb * TILE + st;

            const ulonglong2* dc = reinterpret_cast<const ulonglong2*>(&dbuf[par][0]);
            u64t a0 = 0, a1 = 0, a2 = 0, a3 = 0;
            u64t b0 = 0, b1 = 0, b2 = 0, b3 = 0;
            u64t s0 = 0, s1 = 0, s2 = 0, s3 = 0;
            #pragma unroll
            for (int q = 0; q < 16; q += 2) {
                ulonglong2 v = dc[q];
                ulonglong2 w = dc[q + 1];
                fma2(a0, v.x, PA[2 * q]);     fma2(a1, v.y, PA[2 * q + 1]);
                fma2(a2, w.x, PA[2 * q + 2]); fma2(a3, w.y, PA[2 * q + 3]);
                fma2(b0, v.x, PB[2 * q]);     fma2(b1, v.y, PB[2 * q + 1]);
                fma2(b2, w.x, PB[2 * q + 2]); fma2(b3, w.y, PB[2 * q + 3]);
                add2(s0, s0, v.x); add2(s1, s1, v.y);
                add2(s2, s2, w.x); add2(s3, s3, w.y);
            }
            add2(a0, a0, a1); add2(a2, a2, a3); add2(a0, a0, a2);
            add2(b0, b0, b1); add2(b2, b2, b3); add2(b0, b0, b2);
            add2(s0, s0, s1); add2(s2, s2, s3); add2(s0, s0, s2);
            float accA = unpack_sum(a0);
            float accB = unpack_sum(b0);
            float rho = unpack_sum(s0);
            float f = pow2inv(rho);
            float2 e2 = *reinterpret_cast<const float2*>(&Ebuf[tb & 1][st][j0]);
            int np = par ^ 1;

            if (s >= sfa) {
                if (!bwd) {
                    float wv0 = accA * f * e2.x;
                    float wv1 = accB * f * e2.y;
                    *reinterpret_cast<float2*>(&dbuf[np][j0]) = make_float2(wv0, wv1);
                    if (s >= sout0)
                        *reinterpret_cast<float2*>(&g_dirF[(size_t)s * KST + j0]) =
                            make_float2(wv0, wv1);
                    if (lane == 0) {
                        int t = s - 1;
                        if (t == 0) { g_cF[0] = rho; g_rhoF[0] = rho; }
                        else if (t >= sout0) {
                            g_cF[t] = __fdividef(rho, rnorm);
                            g_rhoF[t] = rho;
                        }
                    }
                } else {
                    float wv0 = accA * f;
                    float wv1 = accB * f;
                    *reinterpret_cast<float2*>(&dbuf[np][j0]) =
                        make_float2(wv0 * e2.x, wv1 * e2.y);
                    if (s >= sout0) {
                        *reinterpret_cast<float2*>(&g_dirB[(size_t)(TLEN - 1 - s) * KST + j0]) =
                            make_float2(wv0, wv1);
                        if (lane == 0) g_fB[s] = f;
                    } else if (s == sout0 - 1) {
                        *reinterpret_cast<float2*>(&g_wtmp[cb * KST + j0]) =
                            make_float2(wv0, wv1);
                    }
                }
                rnorm = f * rho;
            }
            par = np;
            __syncwarp();
        }
    }

    // fwd: final rho/c for t = send-1
    if (!bwd) {
        const ulonglong2* dc = reinterpret_cast<const ulonglong2*>(&dbuf[par][0]);
        u64t s0 = 0, s1 = 0, s2 = 0, s3 = 0;
        #pragma unroll
        for (int q = 0; q < 16; q += 2) {
            ulonglong2 v = dc[q];
            ulonglong2 w = dc[q + 1];
            add2(s0, s0, v.x); add2(s1, s1, v.y);
            add2(s2, s2, w.x); add2(s3, s3, w.y);
        }
        add2(s0, s0, s1); add2(s2, s2, s3); add2(s0, s0, s2);
        float rho = unpack_sum(s0);
        if (lane == 0) {
            g_cF[send - 1] = __fdividef(rho, rnorm);
            g_rhoF[send - 1] = rho;
        }
    }
}

// ---------------------------------------------------------------------------
// rsum (blocks 0..1023) + lam (blocks 1024..1087) fused into one launch
// ---------------------------------------------------------------------------
__global__ void rsum_lam_kernel() {
    if (blockIdx.x < TLEN / 256) {
        int m = blockIdx.x * 256 + threadIdx.x;
        const float4* r = reinterpret_cast<const float4*>(&g_dirB[(size_t)(TLEN - 1 - m) * KST]);
        float s = 0.f;
        #pragma unroll
        for (int i = 0; i < 16; i++) {
            float4 v = r[i];
            s += (v.x + v.y) + (v.z + v.w);
        }
        g_rhoB[m] = s;
    } else {
        int gw = ((blockIdx.x - TLEN / 256) * blockDim.x + threadIdx.x) >> 5;
        int lane = threadIdx.x & 31;
        if (gw >= NCH) return;
        float s = g_wtmp[gw * KST + lane] + g_wtmp[gw * KST + 32 + lane];
        s += __shfl_xor_sync(0xffffffffu, s, 16);
        s += __shfl_xor_sync(0xffffffffu, s, 8);
        s += __shfl_xor_sync(0xffffffffu, s, 4);
        s += __shfl_xor_sync(0xffffffffu, s, 2);
        s += __shfl_xor_sync(0xffffffffu, s, 1);
        if (lane == 0) g_lam[gw] = s;
    }
}

// ---------------------------------------------------------------------------
// Scans. S = f64 prefix sum of v_t = log(eps/c_t) (v computed in f32).
// Prefix-LSE of G_j = -S_j held as (m:f64, s:f32), value = m + log s.
// ---------------------------------------------------------------------------
__global__ void scan_k1() {
    __shared__ double sm[512];
    int fb = blockIdx.x >> 9, blk = blockIdx.x & 511;
    int tid = threadIdx.x, idx = blk * 512 + tid;
    double v;
    if (idx == 0) v = 0.0;
    else if (fb == 0) v = (double)(LOGEPSF - logf(g_cF[idx]));
    else {
        float Rprev = (tid == 0) ? g_lam[blk] : g_rhoB[idx - 1];
        float c = g_rhoB[idx] / (g_fB[idx] * Rprev);
        v = (double)(LOGEPSF - logf(c));
    }
    sm[tid] = v; __syncthreads();
    for (int off = 1; off < 512; off <<= 1) {
        double t = (tid >= off) ? sm[tid - off] : 0.0;
        __syncthreads();
        sm[tid] += t; __syncthreads();
    }
    g_S[fb * TLEN + idx] = sm[tid];
    if (tid == 511) g_part[blockIdx.x] = sm[tid];
}
__global__ void scan_k2() {
    __shared__ double sm[512];
    int tid = threadIdx.x;
    double* p = g_part + blockIdx.x * 512;
    sm[tid] = p[tid]; __syncthreads();
    for (int off = 1; off < 512; off <<= 1) {
        double t = (tid >= off) ? sm[tid - off] : 0.0;
        __syncthreads();
        sm[tid] += t; __syncthreads();
    }
    p[tid] = (tid == 0) ? 0.0 : sm[tid - 1];
}
__global__ void scan_k3() {
    __shared__ double sm_m[512];
    __shared__ float  sm_s[512];
    int fb = blockIdx.x >> 9, blk = blockIdx.x & 511;
    int tid = threadIdx.x, idx = blk * 512 + tid;
    double s_loc = g_S[fb * TLEN + idx] + g_part[blockIdx.x];
    g_S[fb * TLEN + idx] = s_loc;
    double gm;
    if (idx == 0) gm = fb ? -log(64.0) : log1p(EPSV / (double)g_cF[0]);
    else          gm = -s_loc;
    sm_m[tid] = gm; sm_s[tid] = 1.0f;
    __syncthreads();
    for (int off = 1; off < 512; off <<= 1) {
        double pm; float ps;
        if (tid >= off) { pm = sm_m[tid - off]; ps = sm_s[tid - off]; }
        else            { pm = -1e300; ps = 0.f; }
        __syncthreads();
        double cm = sm_m[tid]; float cs = sm_s[tid];
        if (pm > cm) { sm_m[tid] = pm; sm_s[tid] = ps + cs * expf((float)(cm - pm)); }
        else         {                 sm_s[tid] = cs + ps * expf((float)(pm - cm)); }
        __syncthreads();
    }
    g_LM[fb * TLEN + idx] = sm_m[tid];
    g_LS[fb * TLEN + idx] = sm_s[tid];
    if (tid == 511) { g_p2m[blockIdx.x] = sm_m[tid]; g_p2s[blockIdx.x] = sm_s[tid]; }
}
__global__ void scan_k4() {
    __shared__ double sm_m[512];
    __shared__ float  sm_s[512];
    int tid = threadIdx.x;
    int base = blockIdx.x * 512;
    sm_m[tid] = g_p2m[base + tid]; sm_s[tid] = g_p2s[base + tid];
    __syncthreads();
    for (int off = 1; off < 512; off <<= 1) {
        double pm; float ps;
        if (tid >= off) { pm = sm_m[tid - off]; ps = sm_s[tid - off]; }
        else            { pm = -1e300; ps = 0.f; }
        __syncthreads();
        double cm = sm_m[tid]; float cs = sm_s[tid];
        if (pm > cm) { sm_m[tid] = pm; sm_s[tid] = ps + cs * expf((float)(cm - pm)); }
        else         {                 sm_s[tid] = cs + ps * expf((float)(pm - cm)); }
        __syncthreads();
    }
    if (tid == 0) { g_p2m[base] = -1e300; g_p2s[base] = 0.f; }
    else          { g_p2m[base + tid] = sm_m[tid - 1]; g_p2s[base + tid] = sm_s[tid - 1]; }
}
__global__ void scan_k5(float* __restrict__ out) {
    int fb = blockIdx.x >> 9, blk = blockIdx.x & 511;
    int idx = blk * 512 + threadIdx.x;
    double Lm = g_LM[fb * TLEN + idx]; float Ls = g_LS[fb * TLEN + idx];
    double pm = g_p2m[blockIdx.x];     float ps = g_p2s[blockIdx.x];
    double m; float s;
    if (pm > Lm) { m = pm; s = ps + Ls * expf((float)(Lm - pm)); }
    else         { m = Lm; s = Ls + ps * expf((float)(pm - Lm)); }
    double lq = g_S[fb * TLEN + idx] + m + (double)logf(s);
    float rho = fb ? g_rhoB[idx] : g_rhoF[idx];
    float lqf = (lq > 200.0) ? 200.0f : (float)lq;
    float sc = expf(-lqf) / rho;
    if (lq > 150.0) sc = 0.f;
    (fb ? g_scB : g_scF)[idx] = sc;
    if (fb == 0 && idx == TLEN - 1)
        out[(size_t)2 * TLEN * KST] = (float)log(exp(-lq) + EPSV);
}

// ---------------------------------------------------------------------------
// Finalize: skip dir-row loads where the scale is exactly zero (most rows)
// ---------------------------------------------------------------------------
__global__ void finalize_kernel(float* __restrict__ out) {
    size_t i4 = ((size_t)blockIdx.x * 256 + threadIdx.x) * 4;
    int t = (int)(i4 >> 6);
    float sF = g_scF[t];
    float sB = g_scB[TLEN - 1 - t];
    float4 a = make_float4(0.f, 0.f, 0.f, 0.f);
    float4 b = make_float4(0.f, 0.f, 0.f, 0.f);
    if (sF != 0.f) {
        a = *reinterpret_cast<const float4*>(&g_dirF[i4]);
        a.x *= sF; a.y *= sF; a.z *= sF; a.w *= sF;
    }
    if (sB != 0.f) {
        b = *reinterpret_cast<const float4*>(&g_dirB[i4]);
        b.x *= sB; b.y *= sB; b.z *= sB; b.w *= sB;
    }
    *reinterpret_cast<float4*>(&out[i4]) = a;
    *reinterpret_cast<float4*>(&out[(size_t)TLEN * KST + i4]) = b;
}

// ---------------------------------------------------------------------------
extern "C" void kernel_launch(void* const* d_in, const int* in_sizes, int n_in,
                              void* d_out, int out_size) {
    const float* obs      = (const float*)d_in[0];
    const float* blogits  = (const float*)d_in[1];
    const float* pilogits = (const float*)d_in[2];
    const float* means    = (const float*)d_in[3];
    const float* logvars  = (const float*)d_in[4];
    float* out = (float*)d_out;

    pad_kernel<<<1, 32>>>(0);                               // idx 0
    emis_kernel<<<TLEN / 16, 256>>>(obs, means, logvars);   // idx 1
    pk_kernel<<<1, 64>>>(pilogits);                         // idx 2
    chunk_kernel<<<2 * NCH, 32>>>(blogits);                 // idx 3 <- ncu capture slot
    rsum_lam_kernel<<<TLEN / 256 + 64, 256>>>();
    scan_k1<<<1024, 512>>>();
    scan_k2<<<2, 512>>>();
    scan_k3<<<1024, 512>>>();
    scan_k4<<<2, 512>>>();
    scan_k5<<<1024, 512>>>(out);
    finalize_kernel<<<(size_t)TLEN * KST / 1024, 256>>>(out);
}

// round 14
// speedup vs baseline: 1.3118x; 1.0141x over previous
#include <cuda_runtime.h>
#include <math.h>

#define TLEN 262144
#define KST  64
#define FDIM 16
#define LCH  256
#define WARM 64
#define STEPS (WARM + LCH)     // 320
#define TILE 8
#define NTILES (STEPS / TILE)  // 40
#define NCH  (TLEN / LCH)      // 1024
#define EPSV 1e-10
#define LOGEPSF (-23.0258509299f)

// ---- scratch (__device__ globals; no cudaMalloc allowed) ----
__device__ float  g_E   [(size_t)TLEN * KST];
__device__ float  g_P   [KST * KST];   // softmaxed pi, row-major
__device__ float  g_PT  [KST * KST];   // transpose of g_P
__device__ float  g_dirF[(size_t)TLEN * KST];
__device__ float  g_dirB[(size_t)TLEN * KST];
__device__ float  g_cF[TLEN];
__device__ float  g_fB[TLEN];
__device__ float  g_rhoF[TLEN];
__device__ float  g_rhoB[TLEN];
__device__ float  g_wtmp[NCH * KST];   // bwd pre-emission dir at last warm step
__device__ float  g_lam[NCH];          // its sum (boundary handoff scale)
__device__ double g_S[2 * TLEN];       // prefix sums of log(eps/c), fb-major
__device__ double g_LM[2 * TLEN];      // prefix-LSE max part
__device__ float  g_LS[2 * TLEN];      // prefix-LSE sum part (value = m + log s)
__device__ double g_part[1024];
__device__ double g_p2m[1024];
__device__ float  g_p2s[1024];
__device__ float  g_scF[TLEN], g_scB[TLEN];   // g_scB indexed in m-space
__device__ int    g_pad[4];

typedef unsigned long long u64t;

__device__ __forceinline__ void fma2(u64t& acc, u64t a, u64t b) {
    asm("fma.rn.f32x2 %0, %1, %2, %3;" : "=l"(acc) : "l"(a), "l"(b), "l"(acc));
}
__device__ __forceinline__ void add2(u64t& d, u64t a, u64t b) {
    asm("add.rn.f32x2 %0, %1, %2;" : "=l"(d) : "l"(a), "l"(b));
}
__device__ __forceinline__ float unpack_sum(u64t v) {
    float lo, hi;
    asm("mov.b64 {%0, %1}, %2;" : "=f"(lo), "=f"(hi) : "l"(v));
    return lo + hi;
}
__device__ __forceinline__ float pow2inv(float r) {
    unsigned b = __float_as_uint(r);
    unsigned e = (b >> 23) & 0xffu;
    return __uint_as_float((254u - e) << 23);
}

__device__ __forceinline__ void cp16(void* dst, const void* src) {
    unsigned ds = (unsigned)__cvta_generic_to_shared(dst);
    asm volatile("cp.async.ca.shared.global [%0], [%1], 16;" :: "r"(ds), "l"(src));
}
#define CP_COMMIT() asm volatile("cp.async.commit_group;")
#define CP_WAIT(n)  asm volatile("cp.async.wait_group %0;" :: "n"(n))
#define FULLM 0xffffffffu

__device__ __forceinline__ int clampr(int row) {
    row = row < 0 ? 0 : row;
    return row > TLEN - 1 ? TLEN - 1 : row;
}

// ---------------------------------------------------------------------------
__global__ void pad_kernel(int which) {
    if (threadIdx.x == 0) g_pad[which] = which;
}

// ---------------------------------------------------------------------------
// Emission: 16 time rows per block
// ---------------------------------------------------------------------------
__global__ void emis_kernel(const float* __restrict__ obs,
                            const float* __restrict__ means,
                            const float* __restrict__ logvars) {
    __shared__ float mu_s[FDIM][KST];
    __shared__ float iv_s[FDIM][KST];
    __shared__ float ck_s[KST];
    __shared__ float xo_s[16][FDIM];
    const float LOG2PI = 1.8378770664093453f;
    int tid = threadIdx.x;

    for (int idx = tid; idx < KST * FDIM; idx += 256) {
        int k = idx >> 4, f = idx & 15;
        mu_s[f][k] = means[idx];
        iv_s[f][k] = expf(-logvars[idx]);
    }
    if (tid < KST) {
        float s = 0.f;
        #pragma unroll
        for (int f = 0; f < FDIM; f++) s += logvars[tid * FDIM + f];
        ck_s[tid] = -0.5f * s - 0.5f * (float)FDIM * LOG2PI;
    }
    int t0 = blockIdx.x * 16;
    xo_s[tid >> 4][tid & 15] = obs[(size_t)t0 * FDIM + tid];
    __syncthreads();

    int k = tid & 63, tb = tid >> 6;
    #pragma unroll
    for (int i = 0; i < 4; i++) {
        int tl = tb * 4 + i;
        float acc = 0.f;
        #pragma unroll
        for (int f = 0; f < FDIM; f++) {
            float d = xo_s[tl][f] - mu_s[f][k];
            acc = fmaf(d * d, iv_s[f][k], acc);
        }
        g_E[(size_t)(t0 + tl) * KST + k] = expf(-0.5f * acc + ck_s[k]);
    }
}

// ---------------------------------------------------------------------------
// Precompute softmax(P) and its transpose once.
// ---------------------------------------------------------------------------
__global__ void pk_kernel(const float* __restrict__ pi_logits) {
    int r = threadIdx.x;   // 64 threads, one row each
    float row[KST];
    float m = -1e30f;
    #pragma unroll
    for (int i = 0; i < KST; i++) {
        row[i] = pi_logits[r * KST + i];
        m = fmaxf(m, row[i]);
    }
    float s = 0.f;
    #pragma unroll
    for (int i = 0; i < KST; i++) { row[i] = expf(row[i] - m); s += row[i]; }
    float inv = 1.f / s;
    #pragma unroll
    for (int i = 0; i < KST; i++) {
        float v = row[i] * inv;
        g_P[r * KST + i] = v;
        g_PT[i * KST + r] = v;
    }
}

// ---------------------------------------------------------------------------
// Chunk kernel: ONE WARP per chain. Lane owns states j0=2*lane, j0+1.
// rho via 5-shfl butterfly of per-lane partials (overlapped with the dot),
// replacing the redundant per-lane add2 sum tree.
// ---------------------------------------------------------------------------
__global__ void __launch_bounds__(32, 8) chunk_kernel(
    const float* __restrict__ beta_logits) {
    __shared__ __align__(16) float Ebuf[2][TILE][KST];
    __shared__ __align__(16) float dbuf[2][KST];

    int lane = threadIdx.x;
    const bool bwd = (blockIdx.x >= NCH);
    const int cb = bwd ? (int)blockIdx.x - NCH : (int)blockIdx.x;
    const int j0 = lane * 2;

    const int sout0 = cb * LCH;
    const int sfirst0 = sout0 - WARM;
    const int sfa = (cb == 0) ? 1 : sfirst0;
    const int send = sout0 + LCH;

    // prefetch tile 0 (4 cp16 per lane)
    #pragma unroll
    for (int i = 0; i < 4; i++) {
        int f4 = i * 32 + lane;
        int q = f4 >> 4, k0 = (f4 & 15) << 2;
        int row = clampr(bwd ? (TLEN - 1 - (sfirst0 + q)) : (sfirst0 + q));
        cp16(&Ebuf[0][q][k0], g_E + (size_t)row * KST + k0);
    }
    CP_COMMIT();

    // P into registers: 2 rows of (bwd ? g_P : g_PT), packed as f32x2 pairs.
    const float* rowA = (bwd ? g_P : g_PT) + j0 * KST;
    const float* rowB = rowA + KST;
    u64t PA[32], PB[32];
    {
        const ulonglong2* pa = reinterpret_cast<const ulonglong2*>(rowA);
        const ulonglong2* pb = reinterpret_cast<const ulonglong2*>(rowB);
        #pragma unroll
        for (int q = 0; q < 16; q++) {
            ulonglong2 va = pa[q]; PA[2 * q] = va.x; PA[2 * q + 1] = va.y;
            ulonglong2 vb = pb[q]; PB[2 * q] = vb.x; PB[2 * q + 1] = vb.y;
        }
    }

    // ---- init carried state (both parities) + lane partial of its sum ----
    float partial;
    if (!bwd) {
        float w0, w1;
        if (cb == 0) {
            float pr = 1.f; w0 = 0.f; w1 = 0.f;
            for (int j = 0; j <= j0 + 1; j++) {
                float sg = 1.f / (1.f + expf(-beta_logits[j]));
                if (j == j0) w0 = pr * sg;
                else if (j == j0 + 1) w1 = pr * sg;
                pr *= (1.f - sg);
            }
            w0 *= g_E[j0]; w1 *= g_E[j0 + 1];
            *reinterpret_cast<float2*>(&g_dirF[j0]) = make_float2(w0, w1);
        } else {
            w0 = 1.f / 64.f; w1 = 1.f / 64.f;
        }
        *reinterpret_cast<float2*>(&dbuf[0][j0]) = make_float2(w0, w1);
        *reinterpret_cast<float2*>(&dbuf[1][j0]) = make_float2(w0, w1);
        partial = w0 + w1;
    } else {
        float z0, z1;
        if (cb == 0) {
            z0 = (1.f / 64.f) * g_E[(size_t)(TLEN - 1) * KST + j0];
            z1 = (1.f / 64.f) * g_E[(size_t)(TLEN - 1) * KST + j0 + 1];
            *reinterpret_cast<float2*>(&g_dirB[(size_t)(TLEN - 1) * KST + j0]) =
                make_float2(1.f / 64.f, 1.f / 64.f);
        } else {
            int tws = clampr(TLEN - sfirst0);
            z0 = (1.f / 64.f) * g_E[(size_t)tws * KST + j0];
            z1 = (1.f / 64.f) * g_E[(size_t)tws * KST + j0 + 1];
        }
        *reinterpret_cast<float2*>(&dbuf[0][j0]) = make_float2(z0, z1);
        *reinterpret_cast<float2*>(&dbuf[1][j0]) = make_float2(z0, z1);
        partial = z0 + z1;
    }
    __syncwarp();

    float rnorm = 1.f;
    int par = 0;

    for (int tb = 0; tb < NTILES; tb++) {
        if (tb + 1 < NTILES) {
            #pragma unroll
            for (int i = 0; i < 4; i++) {
                int f4 = i * 32 + lane;
                int q = f4 >> 4, k0 = (f4 & 15) << 2;
                int s = sfirst0 + (tb + 1) * TILE + q;
                int row = clampr(bwd ? (TLEN - 1 - s) : s);
                cp16(&Ebuf[(tb + 1) & 1][q][k0], g_E + (size_t)row * KST + k0);
            }
            CP_COMMIT();
            CP_WAIT(1);
        } else {
            CP_WAIT(0);
        }
        __syncwarp();

        #pragma unroll 2
        for (int st = 0; st < TILE; st++) {
            int s = sfirst0 + tb * TILE + st;

            // rho of carried vector via butterfly (overlaps the dot below)
            float r = partial;
            r += __shfl_xor_sync(FULLM, r, 16);
            r += __shfl_xor_sync(FULLM, r, 8);
            r += __shfl_xor_sync(FULLM, r, 4);
            r += __shfl_xor_sync(FULLM, r, 2);
            r += __shfl_xor_sync(FULLM, r, 1);
            float rho = r;
            float f = pow2inv(rho);

            const ulonglong2* dc = reinterpret_cast<const ulonglong2*>(&dbuf[par][0]);
            u64t a0 = 0, a1 = 0, a2 = 0, a3 = 0;
            u64t b0 = 0, b1 = 0, b2 = 0, b3 = 0;
            #pragma unroll
            for (int q = 0; q < 16; q += 2) {
                ulonglong2 v = dc[q];
                ulonglong2 w = dc[q + 1];
                fma2(a0, v.x, PA[2 * q]);     fma2(a1, v.y, PA[2 * q + 1]);
                fma2(a2, w.x, PA[2 * q + 2]); fma2(a3, w.y, PA[2 * q + 3]);
                fma2(b0, v.x, PB[2 * q]);     fma2(b1, v.y, PB[2 * q + 1]);
                fma2(b2, w.x, PB[2 * q + 2]); fma2(b3, w.y, PB[2 * q + 3]);
            }
            add2(a0, a0, a1); add2(a2, a2, a3); add2(a0, a0, a2);
            add2(b0, b0, b1); add2(b2, b2, b3); add2(b0, b0, b2);
            float accA = unpack_sum(a0);
            float accB = unpack_sum(b0);
            float2 e2 = *reinterpret_cast<const float2*>(&Ebuf[tb & 1][st][j0]);
            int np = par ^ 1;

            if (s >= sfa) {
                if (!bwd) {
                    float wv0 = accA * f * e2.x;
                    float wv1 = accB * f * e2.y;
                    *reinterpret_cast<float2*>(&dbuf[np][j0]) = make_float2(wv0, wv1);
                    partial = wv0 + wv1;
                    if (s >= sout0)
                        *reinterpret_cast<float2*>(&g_dirF[(size_t)s * KST + j0]) =
                            make_float2(wv0, wv1);
                    if (lane == 0) {
                        int t = s - 1;
                        if (t == 0) { g_cF[0] = rho; g_rhoF[0] = rho; }
                        else if (t >= sout0) {
                            g_cF[t] = __fdividef(rho, rnorm);
                            g_rhoF[t] = rho;
                        }
                    }
                } else {
                    float wv0 = accA * f;
                    float wv1 = accB * f;
                    float c0 = wv0 * e2.x, c1 = wv1 * e2.y;
                    *reinterpret_cast<float2*>(&dbuf[np][j0]) = make_float2(c0, c1);
                    partial = c0 + c1;
                    if (s >= sout0) {
                        *reinterpret_cast<float2*>(&g_dirB[(size_t)(TLEN - 1 - s) * KST + j0]) =
                            make_float2(wv0, wv1);
                        if (lane == 0) g_fB[s] = f;
                    } else if (s == sout0 - 1) {
                        *reinterpret_cast<float2*>(&g_wtmp[cb * KST + j0]) =
                            make_float2(wv0, wv1);
                    }
                }
                rnorm = f * rho;
            }
            par = np;
            __syncwarp();
        }
    }

    // fwd: final rho/c for t = send-1 (butterfly of last partial)
    if (!bwd) {
        float r = partial;
        r += __shfl_xor_sync(FULLM, r, 16);
        r += __shfl_xor_sync(FULLM, r, 8);
        r += __shfl_xor_sync(FULLM, r, 4);
        r += __shfl_xor_sync(FULLM, r, 2);
        r += __shfl_xor_sync(FULLM, r, 1);
        if (lane == 0) {
            g_cF[send - 1] = __fdividef(r, rnorm);
            g_rhoF[send - 1] = r;
        }
    }
}

// ---------------------------------------------------------------------------
// rsum (blocks 0..1023) + lam (blocks 1024..1151) fused into one launch
// ---------------------------------------------------------------------------
__global__ void rsum_lam_kernel() {
    if (blockIdx.x < TLEN / 256) {
        int m = blockIdx.x * 256 + threadIdx.x;
        const float4* r = reinterpret_cast<const float4*>(&g_dirB[(size_t)(TLEN - 1 - m) * KST]);
        float s = 0.f;
        #pragma unroll
        for (int i = 0; i < 16; i++) {
            float4 v = r[i];
            s += (v.x + v.y) + (v.z + v.w);
        }
        g_rhoB[m] = s;
    } else {
        int gw = ((blockIdx.x - TLEN / 256) * blockDim.x + threadIdx.x) >> 5;
        int lane = threadIdx.x & 31;
        if (gw >= NCH) return;
        float s = g_wtmp[gw * KST + lane] + g_wtmp[gw * KST + 32 + lane];
        s += __shfl_xor_sync(0xffffffffu, s, 16);
        s += __shfl_xor_sync(0xffffffffu, s, 8);
        s += __shfl_xor_sync(0xffffffffu, s, 4);
        s += __shfl_xor_sync(0xffffffffu, s, 2);
        s += __shfl_xor_sync(0xffffffffu, s, 1);
        if (lane == 0) g_lam[gw] = s;
    }
}

// ---------------------------------------------------------------------------
// Scans. S = f64 prefix sum of v_t = log(eps/c_t) (v computed in f32).
// Prefix-LSE of G_j = -S_j held as (m:f64, s:f32), value = m + log s.
// ---------------------------------------------------------------------------
__global__ void scan_k1() {
    __shared__ double sm[512];
    int fb = blockIdx.x >> 9, blk = blockIdx.x & 511;
    int tid = threadIdx.x, idx = blk * 512 + tid;
    double v;
    if (idx == 0) v = 0.0;
    else if (fb == 0) v = (double)(LOGEPSF - logf(g_cF[idx]));
    else {
        // chunk boundary (idx multiple of LCH): use the chunk's own warm-up
        // handoff scale lam[idx/LCH] instead of prev chunk's R.
        float Rprev = ((idx & (LCH - 1)) == 0) ? g_lam[idx / LCH] : g_rhoB[idx - 1];
        float c = g_rhoB[idx] / (g_fB[idx] * Rprev);
        v = (double)(LOGEPSF - logf(c));
    }
    sm[tid] = v; __syncthreads();
    for (int off = 1; off < 512; off <<= 1) {
        double t = (tid >= off) ? sm[tid - off] : 0.0;
        __syncthreads();
        sm[tid] += t; __syncthreads();
    }
    g_S[fb * TLEN + idx] = sm[tid];
    if (tid == 511) g_part[blockIdx.x] = sm[tid];
}
__global__ void scan_k2() {
    __shared__ double sm[512];
    int tid = threadIdx.x;
    double* p = g_part + blockIdx.x * 512;
    sm[tid] = p[tid]; __syncthreads();
    for (int off = 1; off < 512; off <<= 1) {
        double t = (tid >= off) ? sm[tid - off] : 0.0;
        __syncthreads();
        sm[tid] += t; __syncthreads();
    }
    p[tid] = (tid == 0) ? 0.0 : sm[tid - 1];
}
__global__ void scan_k3() {
    __shared__ double sm_m[512];
    __shared__ float  sm_s[512];
    int fb = blockIdx.x >> 9, blk = blockIdx.x & 511;
    int tid = threadIdx.x, idx = blk * 512 + tid;
    double s_loc = g_S[fb * TLEN + idx] + g_part[blockIdx.x];
    g_S[fb * TLEN + idx] = s_loc;
    double gm;
    if (idx == 0) gm = fb ? -log(64.0) : log1p(EPSV / (double)g_cF[0]);
    else          gm = -s_loc;
    sm_m[tid] = gm; sm_s[tid] = 1.0f;
    __syncthreads();
    for (int off = 1; off < 512; off <<= 1) {
        double pm; float ps;
        if (tid >= off) { pm = sm_m[tid - off]; ps = sm_s[tid - off]; }
        else            { pm = -1e300; ps = 0.f; }
        __syncthreads();
        double cm = sm_m[tid]; float cs = sm_s[tid];
        if (pm > cm) { sm_m[tid] = pm; sm_s[tid] = ps + cs * expf((float)(cm - pm)); }
        else         {                 sm_s[tid] = cs + ps * expf((float)(pm - cm)); }
        __syncthreads();
    }
    g_LM[fb * TLEN + idx] = sm_m[tid];
    g_LS[fb * TLEN + idx] = sm_s[tid];
    if (tid == 511) { g_p2m[blockIdx.x] = sm_m[tid]; g_p2s[blockIdx.x] = sm_s[tid]; }
}
__global__ void scan_k4() {
    __shared__ double sm_m[512];
    __shared__ float  sm_s[512];
    int tid = threadIdx.x;
    int base = blockIdx.x * 512;
    sm_m[tid] = g_p2m[base + tid]; sm_s[tid] = g_p2s[base + tid];
    __syncthreads();
    for (int off = 1; off < 512; off <<= 1) {
        double pm; float ps;
        if (tid >= off) { pm = sm_m[tid - off]; ps = sm_s[tid - off]; }
        else            { pm = -1e300; ps = 0.f; }
        __syncthreads();
        double cm = sm_m[tid]; float cs = sm_s[tid];
        if (pm > cm) { sm_m[tid] = pm; sm_s[tid] = ps + cs * expf((float)(cm - pm)); }
        else         {                 sm_s[tid] = cs + ps * expf((float)(pm - cm)); }
        __syncthreads();
    }
    if (tid == 0) { g_p2m[base] = -1e300; g_p2s[base] = 0.f; }
    else          { g_p2m[base + tid] = sm_m[tid - 1]; g_p2s[base + tid] = sm_s[tid - 1]; }
}
__global__ void scan_k5(float* __restrict__ out) {
    int fb = blockIdx.x >> 9, blk = blockIdx.x & 511;
    int idx = blk * 512 + threadIdx.x;
    double Lm = g_LM[fb * TLEN + idx]; float Ls = g_LS[fb * TLEN + idx];
    double pm = g_p2m[blockIdx.x];     float ps = g_p2s[blockIdx.x];
    double m; float s;
    if (pm > Lm) { m = pm; s = ps + Ls * expf((float)(Lm - pm)); }
    else         { m = Lm; s = Ls + ps * expf((float)(pm - Lm)); }
    double lq = g_S[fb * TLEN + idx] + m + (double)logf(s);
    float rho = fb ? g_rhoB[idx] : g_rhoF[idx];
    float lqf = (lq > 200.0) ? 200.0f : (float)lq;
    float sc = expf(-lqf) / rho;
    if (lq > 150.0) sc = 0.f;
    (fb ? g_scB : g_scF)[idx] = sc;
    if (fb == 0 && idx == TLEN - 1)
        out[(size_t)2 * TLEN * KST] = (float)log(exp(-lq) + EPSV);
}

// ---------------------------------------------------------------------------
// Finalize: skip dir-row loads where the scale is exactly zero (most rows)
// ---------------------------------------------------------------------------
__global__ void finalize_kernel(float* __restrict__ out) {
    size_t i4 = ((size_t)blockIdx.x * 256 + threadIdx.x) * 4;
    int t = (int)(i4 >> 6);
    float sF = g_scF[t];
    float sB = g_scB[TLEN - 1 - t];
    float4 a = make_float4(0.f, 0.f, 0.f, 0.f);
    float4 b = make_float4(0.f, 0.f, 0.f, 0.f);
    if (sF != 0.f) {
        a = *reinterpret_cast<const float4*>(&g_dirF[i4]);
        a.x *= sF; a.y *= sF; a.z *= sF; a.w *= sF;
    }
    if (sB != 0.f) {
        b = *reinterpret_cast<const float4*>(&g_dirB[i4]);
        b.x *= sB; b.y *= sB; b.z *= sB; b.w *= sB;
    }
    *reinterpret_cast<float4*>(&out[i4]) = a;
    *reinterpret_cast<float4*>(&out[(size_t)TLEN * KST + i4]) = b;
}

// ---------------------------------------------------------------------------
extern "C" void kernel_launch(void* const* d_in, const int* in_sizes, int n_in,
                              void* d_out, int out_size) {
    const float* obs      = (const float*)d_in[0];
    const float* blogits  = (const float*)d_in[1];
    const float* pilogits = (const float*)d_in[2];
    const float* means    = (const float*)d_in[3];
    const float* logvars  = (const float*)d_in[4];
    float* out = (float*)d_out;

    pad_kernel<<<1, 32>>>(0);                               // idx 0
    emis_kernel<<<TLEN / 16, 256>>>(obs, means, logvars);   // idx 1
    pk_kernel<<<1, 64>>>(pilogits);                         // idx 2
    chunk_kernel<<<2 * NCH, 32>>>(blogits);                 // idx 3 <- ncu capture slot
    rsum_lam_kernel<<<TLEN / 256 + NCH * 32 / 256, 256>>>();
    scan_k1<<<1024, 512>>>();
    scan_k2<<<2, 512>>>();
    scan_k3<<<1024, 512>>>();
    scan_k4<<<2, 512>>>();
    scan_k5<<<1024, 512>>>(out);
    finalize_kernel<<<(size_t)TLEN * KST / 1024, 256>>>(out);
}